// round 7
// baseline (speedup 1.0000x reference)
#include <cuda_runtime.h>
#include <cuda_fp16.h>
#include <cstdint>

#define NB   1024
#define TT   48
#define NPGc 32
#define FFc  5
#define HHc  512
#define EPGc 256
#define NTOT (NB*TT*NPGc)
#define ETOT (NB*TT*EPGc)
#define NGRAPH (NB*TT)
#define SEQW 160
#define TSEQ (TT*SEQW)
#define KTOT 672
#define KPAD 704                   // 11 chunks of 64, 128B-aligned rows
#define SLOT ((size_t)NB*KPAD)
#define NCHUNK 11

// dynamic smem layout for lstm kernel
#define SOFF_BIAS 0                // 512 B
#define SOFF_A    1024             // 3 stages x 16384
#define SOFF_W    (1024 + 3*16384) // 11 chunks x 16384
#define SMEM_SZ   (SOFF_W + NCHUNK*16384)   // 230400 B

// ---------------- static device scratch --------------------------------------------
__device__ __align__(128) float  g_y  [NTOT*FFc];
__device__ __align__(128) __half g_hx [49*NB*KPAD];   // [t][B][ h(512) | seq(160) | pad ]
__device__ __align__(128) __half g_Wc [4*HHc*KPAD];   // packed [Whh|Wih|0] half
__device__ __align__(128) float  g_bc [4*HHc];
__device__ __align__(128) float  g_stat[NB*16];
__device__ __align__(128) unsigned g_flag[8][16];     // [mgrp][hblk] step counters
__device__ unsigned g_done = 0;

__device__ __forceinline__ float sigmf(float x){ return __fdividef(1.f, 1.f + __expf(-x)); }
__device__ __forceinline__ float tanhfast(float x){
    const float e = __expf(2.f*x);
    return 1.f - __fdividef(2.f, e + 1.f);
}

__device__ __forceinline__ void cpasync16(void* dst, const void* src){
    uint32_t d = (uint32_t)__cvta_generic_to_shared(dst);
    asm volatile("cp.async.cg.shared.global [%0], [%1], 16;\n" :: "r"(d), "l"(src));
}
__device__ __forceinline__ void cp_commit(){ asm volatile("cp.async.commit_group;\n"); }
template<int N> __device__ __forceinline__ void cp_wait(){
    asm volatile("cp.async.wait_group %0;\n" :: "n"(N));
}
__device__ __forceinline__ void ldm_x4(uint32_t* r, const void* p){
    uint32_t a = (uint32_t)__cvta_generic_to_shared(p);
    asm volatile("ldmatrix.sync.aligned.m8n8.x4.shared.b16 {%0,%1,%2,%3}, [%4];"
        : "=r"(r[0]), "=r"(r[1]), "=r"(r[2]), "=r"(r[3]) : "r"(a));
}
__device__ __forceinline__ void ldm_x2(uint32_t* r, const void* p){
    uint32_t a = (uint32_t)__cvta_generic_to_shared(p);
    asm volatile("ldmatrix.sync.aligned.m8n8.x2.shared.b16 {%0,%1}, [%2];"
        : "=r"(r[0]), "=r"(r[1]) : "r"(a));
}
__device__ __forceinline__ void mma_f16(float* d, const uint32_t* a, const uint32_t* b){
    asm volatile("mma.sync.aligned.m16n8k16.row.col.f32.f16.f16.f32 "
        "{%0,%1,%2,%3}, {%4,%5,%6,%7}, {%8,%9}, {%0,%1,%2,%3};"
        : "+f"(d[0]), "+f"(d[1]), "+f"(d[2]), "+f"(d[3])
        : "r"(a[0]), "r"(a[1]), "r"(a[2]), "r"(a[3]), "r"(b[0]), "r"(b[1]));
}
__device__ __forceinline__ uint32_t swz(uint32_t off){ return off ^ ((off >> 3) & 0x70); }

// ==================== Kernel 0: pack weights (+bias) to half; zero stats =============
__global__ __launch_bounds__(256) void pack_kernel(
    const float* __restrict__ Wih, const float* __restrict__ Whh,
    const float* __restrict__ bih, const float* __restrict__ bhh)
{
    int idx = blockIdx.x*256 + threadIdx.x;
    if (idx < NB*16) g_stat[idx] = 0.f;
    const int total = 4*HHc*KPAD;
    for (; idx < total; idx += gridDim.x*256){
        const int R = idx / KPAD, k = idx - R*KPAD;
        const int hblk = R >> 7, within = R & 127;
        const int g = within >> 5, hloc = within & 31;
        const int p = g*HHc + hblk*32 + hloc;
        float v = 0.f;
        if (k < HHc)       v = Whh[(size_t)p*HHc + k];
        else if (k < KTOT) v = Wih[(size_t)p*SEQW + (k-HHc)];
        g_Wc[idx] = __float2half(v);
        if (k == 0) g_bc[R] = bih[p] + bhh[p];
    }
}

// ==================== Kernel 1: ChebConv — dense L per graph, warp per graph =========
__global__ __launch_bounds__(256) void cheb_kernel(
    const float* __restrict__ x, const float* __restrict__ ea,
    const int* __restrict__ ei, const float* __restrict__ cw,
    const float* __restrict__ cb)
{
    __shared__ float sL[8][32*33];
    __shared__ float sx[8][160], st1[8][160], sdeg[8][32];
    const int tid = threadIdx.x, lane = tid & 31, wid = tid >> 5;
    const int g  = blockIdx.x*8 + wid;
    const int nb = g * NPGc;
    const int b  = g / TT;
    float* L   = sL[wid];
    float* SX  = sx[wid];
    float* ST1 = st1[wid];
    float* SD  = sdeg[wid];

    #pragma unroll
    for (int i = 0; i < 33; ++i) L[i*32 + lane] = 0.f;
    #pragma unroll
    for (int r = 0; r < 5; ++r) SX[r*32 + lane] = x[(size_t)nb*FFc + r*32 + lane];
    SD[lane] = 0.f;
    __syncwarp();

    int es[8], ed[8];
    float ew[8];
    #pragma unroll
    for (int r = 0; r < 8; ++r){
        const int e = g*EPGc + r*32 + lane;
        es[r] = ei[e]        - nb;
        ed[r] = ei[ETOT + e] - nb;
        ew[r] = ea[e];
        atomicAdd(&SD[es[r]], ew[r]);
    }
    __syncwarp();
    {
        float dv = SD[lane];
        dv = (dv > 0.f) ? rsqrtf(dv) : 0.f;
        __syncwarp();
        SD[lane] = dv;
    }
    __syncwarp();
    #pragma unroll
    for (int r = 0; r < 8; ++r){
        const float nrm = -SD[es[r]] * ew[r] * SD[ed[r]];
        atomicAdd(&L[ed[r]*33 + es[r]], nrm);
    }
    __syncwarp();

    float t1f[5] = {0,0,0,0,0};
    #pragma unroll 4
    for (int s = 0; s < 32; ++s){
        const float l = L[lane*33 + s];
        #pragma unroll
        for (int f = 0; f < 5; ++f) t1f[f] += l * SX[s*5 + f];
    }
    #pragma unroll
    for (int f = 0; f < 5; ++f) ST1[lane*5 + f] = t1f[f];
    __syncwarp();

    float t2f[5] = {0,0,0,0,0};
    #pragma unroll 4
    for (int s = 0; s < 32; ++s){
        const float l = L[lane*33 + s];
        #pragma unroll
        for (int f = 0; f < 5; ++f) t2f[f] += l * ST1[s*5 + f];
    }
    float x0[5];
    #pragma unroll
    for (int f = 0; f < 5; ++f){
        x0[f] = SX[lane*5 + f];
        t2f[f] = 2.f*t2f[f] - x0[f];
    }

    float o[5], s2[5];
    #pragma unroll
    for (int j = 0; j < 5; ++j) o[j] = __ldg(&cb[j]);
    #pragma unroll
    for (int i = 0; i < 5; ++i){
        #pragma unroll
        for (int j = 0; j < 5; ++j)
            o[j] += x0[i]*__ldg(&cw[i*5+j]) + t1f[i]*__ldg(&cw[25+i*5+j]) + t2f[i]*__ldg(&cw[50+i*5+j]);
    }
    #pragma unroll
    for (int j = 0; j < 5; ++j){
        g_y[(size_t)nb*FFc + lane*FFc + j] = o[j];
        s2[j] = o[j]*o[j];
    }
    float s1[5];
    #pragma unroll
    for (int j = 0; j < 5; ++j) s1[j] = o[j];
    #pragma unroll
    for (int off = 16; off; off >>= 1){
        #pragma unroll
        for (int j = 0; j < 5; ++j){
            s1[j] += __shfl_xor_sync(0xffffffffu, s1[j], off);
            s2[j] += __shfl_xor_sync(0xffffffffu, s2[j], off);
        }
    }
    if (lane == 0){
        #pragma unroll
        for (int j = 0; j < 5; ++j){
            atomicAdd(&g_stat[b*16 + j],     s1[j]);
            atomicAdd(&g_stat[b*16 + 8 + j], s2[j]);
        }
    }
}

// ==================== Kernel 2: BN transform (stats precomputed) =====================
__global__ __launch_bounds__(256) void bn_kernel(
    const float* __restrict__ gamma, const float* __restrict__ beta)
{
    const int b = blockIdx.x, tid = threadIdx.x;
    __shared__ float sc[5], sh[5];
    if (tid < 5){
        const float inv = 1.f / (float)(TT*NPGc);
        const float mean = g_stat[b*16 + tid] * inv;
        const float var  = g_stat[b*16 + 8 + tid] * inv - mean*mean;
        const float scl  = gamma[tid] * rsqrtf(var + 1e-5f);
        sc[tid] = scl; sh[tid] = beta[tid] - mean*scl;
    }
    __syncthreads();
    const float* yb = g_y + (size_t)b * TSEQ;
    __half2* hz = (__half2*)(g_hx + (size_t)b*KPAD);
    for (int j = tid; j < HHc/2; j += 256) hz[j] = __half2half2(__float2half(0.f));
    for (int j = tid; j < TT*(KPAD-KTOT); j += 256){
        const int t = j / (KPAD-KTOT), c = j % (KPAD-KTOT);
        g_hx[(size_t)t*SLOT + (size_t)b*KPAD + KTOT + c] = __float2half(0.f);
    }
    for (int nidx = tid; nidx < TT*NPGc; nidx += 256){
        const int t = nidx >> 5, node = nidx & 31;
        const float* p = yb + nidx*FFc;
        __half* ob = g_hx + (size_t)t*SLOT + (size_t)b*KPAD + HHc + node*FFc;
        #pragma unroll
        for (int f = 0; f < 5; ++f) ob[f] = __float2half(sigmf(p[f]*sc[f] + sh[f]));
    }
}

// ==================== Kernel 3: persistent LSTM, 512 threads (16 warps) ==============
// Block tile 128x128 (4 gates x 32 h). Warp grid 4m x 4n: warp tile 32 rows x
// (8 cols per gate x 4 gates).
__global__ __launch_bounds__(512, 1) void lstm_persist_kernel()
{
    extern __shared__ char smem[];
    float* sbias = (float*)(smem + SOFF_BIAS);
    char*  Asm   = smem + SOFF_A;
    char*  Wsm   = smem + SOFF_W;

    const int tid  = threadIdx.x;
    const int lane = tid & 31, warp = tid >> 5;
    const int wm = warp >> 2, wn = warp & 3;          // 4 x 4 warp grid
    const int hblk  = blockIdx.x;                     // 16
    const int mgrp  = blockIdx.y;                     // 8
    const int mbase = mgrp * 128;
    const int hbase = hblk * 32;

    // ---- weights (128 x 704 half) into swizzled smem, once ----
    const __half* Bg = g_Wc + (size_t)(hblk*128)*KPAD;
    for (int i = tid; i < 128*88; i += 512){
        const int r = i / 88, p = i - r*88;
        const int ch = p >> 3, jj = p & 7;
        cpasync16(Wsm + ch*16384 + swz((uint32_t)r*128 + jj*16),
                  Bg + (size_t)r*KPAD + ch*64 + jj*8);
    }
    if (tid < 128) sbias[tid] = g_bc[hblk*128 + tid];
    cp_commit();                                       // group: W

    // ---- precomputed fill addressing (2 pieces per thread) ----
    uint32_t dstoff[2], srcoff[2];
    #pragma unroll
    for (int p = 0; p < 2; ++p){
        const int idx = tid + p*512;
        const int r = idx >> 3, j = idx & 7;
        dstoff[p] = swz((uint32_t)r*128 + j*16);
        srcoff[p] = (uint32_t)r*KPAD + j*8;
    }
    auto fillA = [&](int chunk, int stage, const __half* Ag){
        char* dst = Asm + stage*16384;
        const __half* src = Ag + chunk*64;
        cpasync16(dst + dstoff[0], src + srcoff[0]);
        cpasync16(dst + dstoff[1], src + srcoff[1]);
        cp_commit();
    };

    // prologue: step 0 chunks 8,9 -> stages 0,1
    {
        const __half* Ag0 = g_hx + (size_t)mbase*KPAD;
        fillA(8, 0, Ag0);
        fillA(9, 1, Ag0);
    }

    float c_reg[2][4];
    #pragma unroll
    for (int a=0;a<2;a++) for (int e=0;e<4;e++) c_reg[a][e]=0.f;

    const int gl = lane >> 2, tl = lane & 3;
    // ldmatrix lane addressing (within-chunk offsets, pre-swizzle applied per use)
    const int a_row = lane & 15, a_koff = (lane >> 4) * 8;        // x4 A
    const int b_row = lane & 7,  b_koff = ((lane >> 3) & 1) * 8;  // x2 B (lanes 0-15 used)
    int stg = 0;

    for (int t = 0; t < TT; ++t){
        const __half* Ag  = g_hx + (size_t)t*SLOT + (size_t)mbase*KPAD;
        const __half* Agn = g_hx + (size_t)(t+1)*SLOT + (size_t)mbase*KPAD;

        float acc[2][4][4];
        #pragma unroll
        for (int a=0;a<2;a++) for (int b=0;b<4;b++)
            #pragma unroll
            for (int d=0;d<4;d++) acc[a][b][d]=0.f;

        for (int q = 0; q < NCHUNK; ++q){
            if (t == TT-1 && q == NCHUNK-1) cp_wait<0>(); else cp_wait<1>();
            __syncthreads();

            if (!(t == TT-1 && q >= 9)){
                const int fstage = (stg + 2 >= 3) ? stg - 1 : stg + 2;
                if (q == 0){
                    fillA(10, fstage, Ag);
                } else if (q <= 8){
                    if (q == 1 && t > 0){
                        const unsigned* fp = &g_flag[mgrp][0];
                        unsigned ok;
                        do {
                            unsigned f0,f1,f2,f3,f4,f5,f6,f7;
                            asm volatile("ld.relaxed.gpu.v4.u32 {%0,%1,%2,%3}, [%4];"
                                : "=r"(f0),"=r"(f1),"=r"(f2),"=r"(f3) : "l"(fp));
                            asm volatile("ld.relaxed.gpu.v4.u32 {%0,%1,%2,%3}, [%4];"
                                : "=r"(f4),"=r"(f5),"=r"(f6),"=r"(f7) : "l"(fp+4));
                            unsigned g0,g1,g2,g3,g4,g5,g6,g7;
                            asm volatile("ld.relaxed.gpu.v4.u32 {%0,%1,%2,%3}, [%4];"
                                : "=r"(g0),"=r"(g1),"=r"(g2),"=r"(g3) : "l"(fp+8));
                            asm volatile("ld.relaxed.gpu.v4.u32 {%0,%1,%2,%3}, [%4];"
                                : "=r"(g4),"=r"(g5),"=r"(g6),"=r"(g7) : "l"(fp+12));
                            unsigned mn = min(min(min(f0,f1),min(f2,f3)), min(min(f4,f5),min(f6,f7)));
                            mn = min(mn, min(min(min(g0,g1),min(g2,g3)), min(min(g4,g5),min(g6,g7))));
                            ok = (mn >= (unsigned)t);
                        } while (!ok);
                        __threadfence();
                    }
                    fillA(q-1, fstage, Ag);
                } else {
                    fillA(q-1, fstage, Agn);
                }
            }

            const int c = (q < 3) ? q + 8 : q - 3;
            const char* Wc = Wsm + c*16384;
            const char* Ac = Asm + stg*16384;
            #pragma unroll
            for (int kk = 0; kk < 4; ++kk){
                uint32_t af[2][4];
                #pragma unroll
                for (int mf = 0; mf < 2; ++mf){
                    const uint32_t off = (uint32_t)(wm*32 + mf*16 + a_row)*128
                                       + (uint32_t)(kk*16 + a_koff)*2;
                    ldm_x4(af[mf], Ac + swz(off));
                }
                uint32_t bf[4][2];
                #pragma unroll
                for (int g = 0; g < 4; ++g){
                    const uint32_t off = (uint32_t)(g*32 + wn*8 + b_row)*128
                                       + (uint32_t)(kk*16 + b_koff)*2;
                    ldm_x2(bf[g], Wc + swz(off));
                }
                #pragma unroll
                for (int mf = 0; mf < 2; ++mf)
                    #pragma unroll
                    for (int g = 0; g < 4; ++g)
                        mma_f16(acc[mf][g], af[mf], bf[g]);
            }
            stg = (stg + 1 >= 3) ? 0 : stg + 1;
        }

        // epilogue: gates -> c (regs) -> h (half) into slot t+1
        __half* h_out = g_hx + (size_t)(t+1)*SLOT;
        const int hloc0 = wn*8 + tl*2;
        #pragma unroll
        for (int mf = 0; mf < 2; ++mf){
            #pragma unroll
            for (int rr = 0; rr < 2; ++rr){
                const int row = mbase + wm*32 + mf*16 + gl + rr*8;
                float hv[2];
                #pragma unroll
                for (int j = 0; j < 2; ++j){
                    const int e = rr*2 + j;
                    const int hl = hloc0 + j;
                    const float iv = acc[mf][0][e] + sbias[hl];
                    const float fv = acc[mf][1][e] + sbias[32 + hl];
                    const float gv = acc[mf][2][e] + sbias[64 + hl];
                    const float ov = acc[mf][3][e] + sbias[96 + hl];
                    const float cn = sigmf(fv)*c_reg[mf][e] + sigmf(iv)*tanhfast(gv);
                    c_reg[mf][e] = cn;
                    hv[j] = sigmf(ov)*tanhfast(cn);
                }
                *(__half2*)(h_out + (size_t)row*KPAD + hbase + hloc0) =
                    __halves2half2(__float2half(hv[0]), __float2half(hv[1]));
            }
        }

        __syncthreads();
        if (tid == 0){
            __threadfence();
            asm volatile("st.relaxed.gpu.u32 [%0], %1;"
                :: "l"(&g_flag[mgrp][hblk]), "r"((unsigned)(t+1)) : "memory");
        }
    }

    __syncthreads();
    if (tid == 0){
        const unsigned d = atomicAdd(&g_done, 1u);
        if (d == 127u){
            for (int i = 0; i < 8; ++i)
                for (int j = 0; j < 16; ++j) g_flag[i][j] = 0u;
            g_done = 0u;
            __threadfence();
        }
    }
}

// ==================== Kernel 4: final linear, 4 samples per block ====================
__global__ __launch_bounds__(256) void final_kernel(
    const float* __restrict__ linW, const float* __restrict__ linb,
    float* __restrict__ outp)
{
    const int tid = threadIdx.x, lane = tid & 31, warp = tid >> 5;
    const int b0 = blockIdx.x * 4;
    float acc[4][4];
    #pragma unroll
    for (int s = 0; s < 4; ++s)
        #pragma unroll
        for (int o = 0; o < 4; ++o) acc[s][o] = 0.f;

    for (int idx = tid; idx < TT*HHc; idx += 256){
        const int tq = idx >> 9, h = idx & 511;
        const float w0 = __ldg(&linW[idx]);
        const float w1 = __ldg(&linW[TT*HHc + idx]);
        const float w2 = __ldg(&linW[2*TT*HHc + idx]);
        const float w3 = __ldg(&linW[3*TT*HHc + idx]);
        const __half* hp = g_hx + (size_t)(tq+1)*SLOT + h;
        #pragma unroll
        for (int s = 0; s < 4; ++s){
            const float v = sigmf(__half2float(hp[(size_t)(b0+s)*KPAD]));
            acc[s][0] += v*w0; acc[s][1] += v*w1;
            acc[s][2] += v*w2; acc[s][3] += v*w3;
        }
    }
    #pragma unroll
    for (int off = 16; off; off >>= 1)
        #pragma unroll
        for (int s = 0; s < 4; ++s)
            #pragma unroll
            for (int o = 0; o < 4; ++o)
                acc[s][o] += __shfl_xor_sync(0xffffffffu, acc[s][o], off);

    __shared__ float red[8][16];
    if (lane == 0){
        #pragma unroll
        for (int s = 0; s < 4; ++s)
            #pragma unroll
            for (int o = 0; o < 4; ++o) red[warp][s*4+o] = acc[s][o];
    }
    __syncthreads();
    if (tid < 16){
        float sum = 0.f;
        #pragma unroll
        for (int w = 0; w < 8; ++w) sum += red[w][tid];
        const int s = tid >> 2, o = tid & 3;
        outp[(b0 + s)*4 + o] = sigmf(sum + __ldg(&linb[o]));
    }
}

// =====================================================================================
extern "C" void kernel_launch(void* const* d_in, const int* in_sizes, int n_in,
                              void* d_out, int out_size)
{
    const float* x     = (const float*)d_in[0];
    const float* ea    = (const float*)d_in[1];
    const float* cw    = (const float*)d_in[2];
    const float* cb    = (const float*)d_in[3];
    const float* gamma = (const float*)d_in[4];
    const float* beta  = (const float*)d_in[5];
    const float* Wih   = (const float*)d_in[6];
    const float* Whh   = (const float*)d_in[7];
    const float* bih   = (const float*)d_in[8];
    const float* bhh   = (const float*)d_in[9];
    const float* linW  = (const float*)d_in[10];
    const float* linb  = (const float*)d_in[11];
    const int*   ei    = (const int*)  d_in[12];
    float* outp = (float*)d_out;

    cudaFuncSetAttribute(lstm_persist_kernel,
        cudaFuncAttributeMaxDynamicSharedMemorySize, SMEM_SZ);

    pack_kernel<<<1024, 256>>>(Wih, Whh, bih, bhh);
    cheb_kernel<<<NGRAPH/8, 256>>>(x, ea, ei, cw, cb);
    bn_kernel<<<NB, 256>>>(gamma, beta);
    lstm_persist_kernel<<<dim3(16, 8), 512, SMEM_SZ>>>();
    final_kernel<<<NB/4, 256>>>(linW, linb, outp);
}

// round 8
// speedup vs baseline: 1.0107x; 1.0107x over previous
#include <cuda_runtime.h>
#include <cuda_fp16.h>
#include <cstdint>

#define NB   1024
#define TT   48
#define NPGc 32
#define FFc  5
#define HHc  512
#define EPGc 256
#define NTOT (NB*TT*NPGc)
#define ETOT (NB*TT*EPGc)
#define NGRAPH (NB*TT)
#define SEQW 160
#define TSEQ (TT*SEQW)
#define KTOT 672
#define KPAD 704                   // 11 full chunks of 64, 128B-aligned rows
#define SLOT ((size_t)NB*KPAD)
#define NCHUNK 11

// dynamic smem layout for lstm kernel
#define SOFF_BIAS 0                // 512 B
#define SOFF_A    1024             // 3 stages x 16384
#define SOFF_W    (1024 + 3*16384) // 11 chunks x 16384
#define SMEM_SZ   (SOFF_W + NCHUNK*16384)   // 230400 B

// ---------------- static device scratch --------------------------------------------
__device__ __align__(128) float  g_y  [NTOT*FFc];
__device__ __align__(128) __half g_hx [49*NB*KPAD];   // [t][B][ h(512) | seq(160) | pad ]
__device__ __align__(128) __half g_Wc [4*HHc*KPAD];   // packed [Whh|Wih|0] half
__device__ __align__(128) float  g_bc [4*HHc];
__device__ __align__(128) float  g_stat[NB*16];
__device__ __align__(128) unsigned g_flag[8][16];     // [mgrp][hblk] step counters
__device__ unsigned g_done = 0;

__device__ __forceinline__ float sigmf(float x){ return __fdividef(1.f, 1.f + __expf(-x)); }
__device__ __forceinline__ float tanhfast(float x){
    const float e = __expf(2.f*x);
    return 1.f - __fdividef(2.f, e + 1.f);
}

__device__ __forceinline__ void cpasync16(void* dst, const void* src){
    uint32_t d = (uint32_t)__cvta_generic_to_shared(dst);
    asm volatile("cp.async.cg.shared.global [%0], [%1], 16;\n" :: "r"(d), "l"(src));
}
__device__ __forceinline__ void cp_commit(){ asm volatile("cp.async.commit_group;\n"); }
template<int N> __device__ __forceinline__ void cp_wait(){
    asm volatile("cp.async.wait_group %0;\n" :: "n"(N));
}
__device__ __forceinline__ void ldm_x4(uint32_t* r, const void* p){
    uint32_t a = (uint32_t)__cvta_generic_to_shared(p);
    asm volatile("ldmatrix.sync.aligned.m8n8.x4.shared.b16 {%0,%1,%2,%3}, [%4];"
        : "=r"(r[0]), "=r"(r[1]), "=r"(r[2]), "=r"(r[3]) : "r"(a));
}
__device__ __forceinline__ void mma_f16(float* d, const uint32_t* a, const uint32_t* b){
    asm volatile("mma.sync.aligned.m16n8k16.row.col.f32.f16.f16.f32 "
        "{%0,%1,%2,%3}, {%4,%5,%6,%7}, {%8,%9}, {%0,%1,%2,%3};"
        : "+f"(d[0]), "+f"(d[1]), "+f"(d[2]), "+f"(d[3])
        : "r"(a[0]), "r"(a[1]), "r"(a[2]), "r"(a[3]), "r"(b[0]), "r"(b[1]));
}
__device__ __forceinline__ uint32_t swz(uint32_t off){ return off ^ ((off >> 3) & 0x70); }

// ==================== Kernel 0: pack weights (+bias) to half; zero stats =============
__global__ __launch_bounds__(256) void pack_kernel(
    const float* __restrict__ Wih, const float* __restrict__ Whh,
    const float* __restrict__ bih, const float* __restrict__ bhh)
{
    int idx = blockIdx.x*256 + threadIdx.x;
    if (idx < NB*16) g_stat[idx] = 0.f;
    const int total = 4*HHc*KPAD;
    for (; idx < total; idx += gridDim.x*256){
        const int R = idx / KPAD, k = idx - R*KPAD;
        const int hblk = R >> 7, within = R & 127;
        const int g = within >> 5, hloc = within & 31;
        const int p = g*HHc + hblk*32 + hloc;
        float v = 0.f;
        if (k < HHc)       v = Whh[(size_t)p*HHc + k];
        else if (k < KTOT) v = Wih[(size_t)p*SEQW + (k-HHc)];
        g_Wc[idx] = __float2half(v);
        if (k == 0) g_bc[R] = bih[p] + bhh[p];
    }
}

// ==================== Kernel 1: ChebConv — dense L per graph, warp per graph =========
__global__ __launch_bounds__(256) void cheb_kernel(
    const float* __restrict__ x, const float* __restrict__ ea,
    const int* __restrict__ ei, const float* __restrict__ cw,
    const float* __restrict__ cb)
{
    __shared__ float sL[8][32*33];
    __shared__ float sx[8][160], st1[8][160], sdeg[8][32];
    const int tid = threadIdx.x, lane = tid & 31, wid = tid >> 5;
    const int g  = blockIdx.x*8 + wid;
    const int nb = g * NPGc;
    const int b  = g / TT;
    float* L   = sL[wid];
    float* SX  = sx[wid];
    float* ST1 = st1[wid];
    float* SD  = sdeg[wid];

    #pragma unroll
    for (int i = 0; i < 33; ++i) L[i*32 + lane] = 0.f;
    #pragma unroll
    for (int r = 0; r < 5; ++r) SX[r*32 + lane] = x[(size_t)nb*FFc + r*32 + lane];
    SD[lane] = 0.f;
    __syncwarp();

    int es[8], ed[8];
    float ew[8];
    #pragma unroll
    for (int r = 0; r < 8; ++r){
        const int e = g*EPGc + r*32 + lane;
        es[r] = ei[e]        - nb;
        ed[r] = ei[ETOT + e] - nb;
        ew[r] = ea[e];
        atomicAdd(&SD[es[r]], ew[r]);
    }
    __syncwarp();
    {
        float dv = SD[lane];
        dv = (dv > 0.f) ? rsqrtf(dv) : 0.f;
        __syncwarp();
        SD[lane] = dv;
    }
    __syncwarp();
    #pragma unroll
    for (int r = 0; r < 8; ++r){
        const float nrm = -SD[es[r]] * ew[r] * SD[ed[r]];
        atomicAdd(&L[ed[r]*33 + es[r]], nrm);
    }
    __syncwarp();

    float t1f[5] = {0,0,0,0,0};
    #pragma unroll 4
    for (int s = 0; s < 32; ++s){
        const float l = L[lane*33 + s];
        #pragma unroll
        for (int f = 0; f < 5; ++f) t1f[f] += l * SX[s*5 + f];
    }
    #pragma unroll
    for (int f = 0; f < 5; ++f) ST1[lane*5 + f] = t1f[f];
    __syncwarp();

    float t2f[5] = {0,0,0,0,0};
    #pragma unroll 4
    for (int s = 0; s < 32; ++s){
        const float l = L[lane*33 + s];
        #pragma unroll
        for (int f = 0; f < 5; ++f) t2f[f] += l * ST1[s*5 + f];
    }
    float x0[5];
    #pragma unroll
    for (int f = 0; f < 5; ++f){
        x0[f] = SX[lane*5 + f];
        t2f[f] = 2.f*t2f[f] - x0[f];
    }

    float o[5], s2[5];
    #pragma unroll
    for (int j = 0; j < 5; ++j) o[j] = __ldg(&cb[j]);
    #pragma unroll
    for (int i = 0; i < 5; ++i){
        #pragma unroll
        for (int j = 0; j < 5; ++j)
            o[j] += x0[i]*__ldg(&cw[i*5+j]) + t1f[i]*__ldg(&cw[25+i*5+j]) + t2f[i]*__ldg(&cw[50+i*5+j]);
    }
    #pragma unroll
    for (int j = 0; j < 5; ++j){
        g_y[(size_t)nb*FFc + lane*FFc + j] = o[j];
        s2[j] = o[j]*o[j];
    }
    float s1[5];
    #pragma unroll
    for (int j = 0; j < 5; ++j) s1[j] = o[j];
    #pragma unroll
    for (int off = 16; off; off >>= 1){
        #pragma unroll
        for (int j = 0; j < 5; ++j){
            s1[j] += __shfl_xor_sync(0xffffffffu, s1[j], off);
            s2[j] += __shfl_xor_sync(0xffffffffu, s2[j], off);
        }
    }
    if (lane == 0){
        #pragma unroll
        for (int j = 0; j < 5; ++j){
            atomicAdd(&g_stat[b*16 + j],     s1[j]);
            atomicAdd(&g_stat[b*16 + 8 + j], s2[j]);
        }
    }
}

// ==================== Kernel 2: BN transform (stats precomputed) =====================
__global__ __launch_bounds__(256) void bn_kernel(
    const float* __restrict__ gamma, const float* __restrict__ beta)
{
    const int b = blockIdx.x, tid = threadIdx.x;
    __shared__ float sc[5], sh[5];
    if (tid < 5){
        const float inv = 1.f / (float)(TT*NPGc);
        const float mean = g_stat[b*16 + tid] * inv;
        const float var  = g_stat[b*16 + 8 + tid] * inv - mean*mean;
        const float scl  = gamma[tid] * rsqrtf(var + 1e-5f);
        sc[tid] = scl; sh[tid] = beta[tid] - mean*scl;
    }
    __syncthreads();
    const float* yb = g_y + (size_t)b * TSEQ;
    __half2* hz = (__half2*)(g_hx + (size_t)b*KPAD);
    for (int j = tid; j < HHc/2; j += 256) hz[j] = __half2half2(__float2half(0.f));
    for (int j = tid; j < TT*(KPAD-KTOT); j += 256){
        const int t = j / (KPAD-KTOT), c = j % (KPAD-KTOT);
        g_hx[(size_t)t*SLOT + (size_t)b*KPAD + KTOT + c] = __float2half(0.f);
    }
    for (int nidx = tid; nidx < TT*NPGc; nidx += 256){
        const int t = nidx >> 5, node = nidx & 31;
        const float* p = yb + nidx*FFc;
        __half* ob = g_hx + (size_t)t*SLOT + (size_t)b*KPAD + HHc + node*FFc;
        #pragma unroll
        for (int f = 0; f < 5; ++f) ob[f] = __float2half(sigmf(p[f]*sc[f] + sh[f]));
    }
}

// ==================== Kernel 3: persistent LSTM (round-5 core, pairwise flags) =======
// 256 threads, warp grid 4m x 2n, block tile 128 x 128 (4 gates x 32 h).
__global__ __launch_bounds__(256, 1) void lstm_persist_kernel()
{
    extern __shared__ char smem[];
    float* sbias = (float*)(smem + SOFF_BIAS);
    char*  Asm   = smem + SOFF_A;
    char*  Wsm   = smem + SOFF_W;

    const int tid  = threadIdx.x;
    const int lane = tid & 31, warp = tid >> 5;
    const int wm = warp >> 1, wn = warp & 1;          // 4 x 2 warp grid
    const int hblk  = blockIdx.x;                     // 16
    const int mgrp  = blockIdx.y;                     // 8
    const int mbase = mgrp * 128;
    const int hbase = hblk * 32;

    // ---- weights (128 x 704 half) into swizzled smem, once ----
    const __half* Bg = g_Wc + (size_t)(hblk*128)*KPAD;
    for (int i = tid; i < 128*88; i += 256){
        const int r = i / 88, p = i - r*88;
        const int ch = p >> 3, jj = p & 7;
        cpasync16(Wsm + ch*16384 + swz((uint32_t)r*128 + jj*16),
                  Bg + (size_t)r*KPAD + ch*64 + jj*8);
    }
    if (tid < 128) sbias[tid] = g_bc[hblk*128 + tid];
    cp_commit();                                       // group: W

    // ---- precomputed fill addressing (4 pieces per thread) ----
    uint32_t dstoff[4], srcoff[4];
    #pragma unroll
    for (int p = 0; p < 4; ++p){
        const int idx = tid + p*256;
        const int r = idx >> 3, j = idx & 7;
        dstoff[p] = swz((uint32_t)r*128 + j*16);
        srcoff[p] = (uint32_t)r*KPAD + j*8;
    }
    auto fillA = [&](int chunk, int stage, const __half* Ag){
        char* dst = Asm + stage*16384;
        const __half* src = Ag + chunk*64;
        #pragma unroll
        for (int p = 0; p < 4; ++p) cpasync16(dst + dstoff[p], src + srcoff[p]);
        cp_commit();
    };

    // prologue: step 0 chunks 8,9 -> stages 0,1
    {
        const __half* Ag0 = g_hx + (size_t)mbase*KPAD;
        fillA(8, 0, Ag0);
        fillA(9, 1, Ag0);
    }

    float c_reg[2][2][4];
    #pragma unroll
    for (int a=0;a<2;a++) for (int b=0;b<2;b++) for (int e=0;e<4;e++) c_reg[a][b][e]=0.f;

    const int gl = lane >> 2, tl = lane & 3;
    int stg = 0;

    for (int t = 0; t < TT; ++t){
        const __half* Ag  = g_hx + (size_t)t*SLOT + (size_t)mbase*KPAD;
        const __half* Agn = g_hx + (size_t)(t+1)*SLOT + (size_t)mbase*KPAD;

        float acc[2][4][2][4];
        #pragma unroll
        for (int a=0;a<2;a++) for (int b=0;b<4;b++) for (int c=0;c<2;c++)
            #pragma unroll
            for (int d=0;d<4;d++) acc[a][b][c][d]=0.f;

        for (int q = 0; q < NCHUNK; ++q){
            if (t == TT-1 && q == NCHUNK-1) cp_wait<0>(); else cp_wait<1>();
            __syncthreads();

            if (!(t == TT-1 && q >= 9)){
                const int fstage = (stg + 2 >= 3) ? stg - 1 : stg + 2;
                if (q == 0){
                    fillA(10, fstage, Ag);
                } else if (q <= 8){
                    // h chunk (q-1): cols [64(q-1),64q) produced by hblk 2(q-1), 2q-1
                    if (t > 0){
                        const unsigned* fp = &g_flag[mgrp][2*(q-1)];
                        unsigned f0, f1;
                        do {
                            asm volatile("ld.relaxed.gpu.v2.u32 {%0,%1}, [%2];"
                                : "=r"(f0), "=r"(f1) : "l"(fp));
                        } while (min(f0, f1) < (unsigned)t);
                        __threadfence();
                    }
                    fillA(q-1, fstage, Ag);
                } else {
                    fillA(q-1, fstage, Agn);
                }
            }

            const int c = (q < 3) ? q + 8 : q - 3;
            const char* Wc = Wsm + c*16384;
            const char* Ac = Asm + stg*16384;
            #pragma unroll
            for (int kk = 0; kk < 4; ++kk){
                uint32_t af[2][4];
                #pragma unroll
                for (int mf = 0; mf < 2; ++mf){
                    const uint32_t off = (uint32_t)(wm*32 + mf*16 + (lane&15))*128
                                       + (uint32_t)(kk*16 + ((lane>>4)<<3))*2;
                    ldm_x4(af[mf], Ac + swz(off));
                }
                uint32_t bf[4][4];
                #pragma unroll
                for (int g = 0; g < 4; ++g){
                    const uint32_t off = (uint32_t)(g*32 + wn*16 + (lane&7) + ((lane>>4)&1)*8)*128
                                       + (uint32_t)(kk*16 + ((lane>>3)&1)*8)*2;
                    ldm_x4(bf[g], Wc + swz(off));
                }
                #pragma unroll
                for (int mf = 0; mf < 2; ++mf)
                    #pragma unroll
                    for (int g = 0; g < 4; ++g){
                        mma_f16(acc[mf][g][0], af[mf], bf[g] + 0);
                        mma_f16(acc[mf][g][1], af[mf], bf[g] + 2);
                    }
            }
            stg = (stg + 1 >= 3) ? 0 : stg + 1;
        }

        // epilogue: gates -> c (regs) -> h (half) into slot t+1
        __half* h_out = g_hx + (size_t)(t+1)*SLOT;
        #pragma unroll
        for (int mf = 0; mf < 2; ++mf){
            #pragma unroll
            for (int nf = 0; nf < 2; ++nf){
                const int hloc0 = wn*16 + nf*8 + tl*2;
                #pragma unroll
                for (int rr = 0; rr < 2; ++rr){
                    const int row = mbase + wm*32 + mf*16 + gl + rr*8;
                    float hv[2];
                    #pragma unroll
                    for (int j = 0; j < 2; ++j){
                        const int e = rr*2 + j;
                        const int hl = hloc0 + j;
                        const float iv = acc[mf][0][nf][e] + sbias[hl];
                        const float fv = acc[mf][1][nf][e] + sbias[32 + hl];
                        const float gv = acc[mf][2][nf][e] + sbias[64 + hl];
                        const float ov = acc[mf][3][nf][e] + sbias[96 + hl];
                        const float cn = sigmf(fv)*c_reg[mf][nf][e] + sigmf(iv)*tanhfast(gv);
                        c_reg[mf][nf][e] = cn;
                        hv[j] = sigmf(ov)*tanhfast(cn);
                    }
                    *(__half2*)(h_out + (size_t)row*KPAD + hbase + hloc0) =
                        __halves2half2(__float2half(hv[0]), __float2half(hv[1]));
                }
            }
        }

        __syncthreads();
        if (tid == 0){
            __threadfence();
            asm volatile("st.relaxed.gpu.u32 [%0], %1;"
                :: "l"(&g_flag[mgrp][hblk]), "r"((unsigned)(t+1)) : "memory");
        }
    }

    __syncthreads();
    if (tid == 0){
        const unsigned d = atomicAdd(&g_done, 1u);
        if (d == 127u){
            for (int i = 0; i < 8; ++i)
                for (int j = 0; j < 16; ++j) g_flag[i][j] = 0u;
            g_done = 0u;
            __threadfence();
        }
    }
}

// ==================== Kernel 4: final linear, 4 samples per block ====================
__global__ __launch_bounds__(256) void final_kernel(
    const float* __restrict__ linW, const float* __restrict__ linb,
    float* __restrict__ outp)
{
    const int tid = threadIdx.x, lane = tid & 31, warp = tid >> 5;
    const int b0 = blockIdx.x * 4;
    float acc[4][4];
    #pragma unroll
    for (int s = 0; s < 4; ++s)
        #pragma unroll
        for (int o = 0; o < 4; ++o) acc[s][o] = 0.f;

    for (int idx = tid; idx < TT*HHc; idx += 256){
        const int tq = idx >> 9, h = idx & 511;
        const float w0 = __ldg(&linW[idx]);
        const float w1 = __ldg(&linW[TT*HHc + idx]);
        const float w2 = __ldg(&linW[2*TT*HHc + idx]);
        const float w3 = __ldg(&linW[3*TT*HHc + idx]);
        const __half* hp = g_hx + (size_t)(tq+1)*SLOT + h;
        #pragma unroll
        for (int s = 0; s < 4; ++s){
            const float v = sigmf(__half2float(hp[(size_t)(b0+s)*KPAD]));
            acc[s][0] += v*w0; acc[s][1] += v*w1;
            acc[s][2] += v*w2; acc[s][3] += v*w3;
        }
    }
    #pragma unroll
    for (int off = 16; off; off >>= 1)
        #pragma unroll
        for (int s = 0; s < 4; ++s)
            #pragma unroll
            for (int o = 0; o < 4; ++o)
                acc[s][o] += __shfl_xor_sync(0xffffffffu, acc[s][o], off);

    __shared__ float red[8][16];
    if (lane == 0){
        #pragma unroll
        for (int s = 0; s < 4; ++s)
            #pragma unroll
            for (int o = 0; o < 4; ++o) red[warp][s*4+o] = acc[s][o];
    }
    __syncthreads();
    if (tid < 16){
        float sum = 0.f;
        #pragma unroll
        for (int w = 0; w < 8; ++w) sum += red[w][tid];
        const int s = tid >> 2, o = tid & 3;
        outp[(b0 + s)*4 + o] = sigmf(sum + __ldg(&linb[o]));
    }
}

// =====================================================================================
extern "C" void kernel_launch(void* const* d_in, const int* in_sizes, int n_in,
                              void* d_out, int out_size)
{
    const float* x     = (const float*)d_in[0];
    const float* ea    = (const float*)d_in[1];
    const float* cw    = (const float*)d_in[2];
    const float* cb    = (const float*)d_in[3];
    const float* gamma = (const float*)d_in[4];
    const float* beta  = (const float*)d_in[5];
    const float* Wih   = (const float*)d_in[6];
    const float* Whh   = (const float*)d_in[7];
    const float* bih   = (const float*)d_in[8];
    const float* bhh   = (const float*)d_in[9];
    const float* linW  = (const float*)d_in[10];
    const float* linb  = (const float*)d_in[11];
    const int*   ei    = (const int*)  d_in[12];
    float* outp = (float*)d_out;

    cudaFuncSetAttribute(lstm_persist_kernel,
        cudaFuncAttributeMaxDynamicSharedMemorySize, SMEM_SZ);

    pack_kernel<<<1024, 256>>>(Wih, Whh, bih, bhh);
    cheb_kernel<<<NGRAPH/8, 256>>>(x, ea, ei, cw, cb);
    bn_kernel<<<NB, 256>>>(gamma, beta);
    lstm_persist_kernel<<<dim3(16, 8), 256, SMEM_SZ>>>();
    final_kernel<<<NB/4, 256>>>(linW, linb, outp);
}

// round 9
// speedup vs baseline: 1.0730x; 1.0617x over previous
#include <cuda_runtime.h>
#include <cuda_fp16.h>
#include <cstdint>

#define NB   1024
#define TT   48
#define NPGc 32
#define FFc  5
#define HHc  512
#define EPGc 256
#define NTOT (NB*TT*NPGc)
#define ETOT (NB*TT*EPGc)
#define NGRAPH (NB*TT)
#define SEQW 160
#define TSEQ (TT*SEQW)
#define KTOT 672
#define KPAD 704                   // 11 full chunks of 64, 128B-aligned rows
#define SLOT ((size_t)NB*KPAD)
#define NCHUNK 11

// dynamic smem layout for lstm kernel
#define SOFF_BIAS 0                // 512 B
#define SOFF_A    1024             // 3 stages x 16384
#define SOFF_W    (1024 + 3*16384) // 11 chunks x 16384
#define SMEM_SZ   (SOFF_W + NCHUNK*16384)   // 230400 B

// ---------------- static device scratch --------------------------------------------
__device__ __align__(128) float  g_y  [NTOT*FFc];
__device__ __align__(128) __half g_hx [49*NB*KPAD];   // [t][B][ h(512) | seq(160) | pad ]
__device__ __align__(128) __half g_Wc [4*HHc*KPAD];   // packed [Whh|Wih|0] half
__device__ __align__(128) float  g_bc [4*HHc];
__device__ __align__(128) float  g_stat[NB*16];
__device__ __align__(128) unsigned g_flag[8][16];     // [mgrp][hblk] step counters
__device__ unsigned g_done = 0;

__device__ __forceinline__ float sigmf(float x){ return __fdividef(1.f, 1.f + __expf(-x)); }
__device__ __forceinline__ float tanhfast(float x){
    const float e = __expf(2.f*x);
    return 1.f - __fdividef(2.f, e + 1.f);
}

__device__ __forceinline__ void cpasync16(void* dst, const void* src){
    uint32_t d = (uint32_t)__cvta_generic_to_shared(dst);
    asm volatile("cp.async.cg.shared.global [%0], [%1], 16;\n" :: "r"(d), "l"(src));
}
__device__ __forceinline__ void cp_commit(){ asm volatile("cp.async.commit_group;\n"); }
template<int N> __device__ __forceinline__ void cp_wait(){
    asm volatile("cp.async.wait_group %0;\n" :: "n"(N));
}
__device__ __forceinline__ void ldm_x4(uint32_t* r, const void* p){
    uint32_t a = (uint32_t)__cvta_generic_to_shared(p);
    asm volatile("ldmatrix.sync.aligned.m8n8.x4.shared.b16 {%0,%1,%2,%3}, [%4];"
        : "=r"(r[0]), "=r"(r[1]), "=r"(r[2]), "=r"(r[3]) : "r"(a));
}
__device__ __forceinline__ void mma_f16(float* d, const uint32_t* a, const uint32_t* b){
    asm volatile("mma.sync.aligned.m16n8k16.row.col.f32.f16.f16.f32 "
        "{%0,%1,%2,%3}, {%4,%5,%6,%7}, {%8,%9}, {%0,%1,%2,%3};"
        : "+f"(d[0]), "+f"(d[1]), "+f"(d[2]), "+f"(d[3])
        : "r"(a[0]), "r"(a[1]), "r"(a[2]), "r"(a[3]), "r"(b[0]), "r"(b[1]));
}
__device__ __forceinline__ uint32_t swz(uint32_t off){ return off ^ ((off >> 3) & 0x70); }

// ==================== Kernel 0: pack weights (+bias) to half; zero stats =============
__global__ __launch_bounds__(256) void pack_kernel(
    const float* __restrict__ Wih, const float* __restrict__ Whh,
    const float* __restrict__ bih, const float* __restrict__ bhh)
{
    int idx = blockIdx.x*256 + threadIdx.x;
    if (idx < NB*16) g_stat[idx] = 0.f;
    const int total = 4*HHc*KPAD;
    for (; idx < total; idx += gridDim.x*256){
        const int R = idx / KPAD, k = idx - R*KPAD;
        const int hblk = R >> 7, within = R & 127;
        const int g = within >> 5, hloc = within & 31;
        const int p = g*HHc + hblk*32 + hloc;
        float v = 0.f;
        if (k < HHc)       v = Whh[(size_t)p*HHc + k];
        else if (k < KTOT) v = Wih[(size_t)p*SEQW + (k-HHc)];
        g_Wc[idx] = __float2half(v);
        if (k == 0) g_bc[R] = bih[p] + bhh[p];
    }
}

// ==================== Kernel 1: ChebConv — dense L per graph, warp per graph =========
__global__ __launch_bounds__(256) void cheb_kernel(
    const float* __restrict__ x, const float* __restrict__ ea,
    const int* __restrict__ ei, const float* __restrict__ cw,
    const float* __restrict__ cb)
{
    __shared__ float sL[8][32*33];
    __shared__ float sx[8][160], st1[8][160], sdeg[8][32];
    const int tid = threadIdx.x, lane = tid & 31, wid = tid >> 5;
    const int g  = blockIdx.x*8 + wid;
    const int nb = g * NPGc;
    const int b  = g / TT;
    float* L   = sL[wid];
    float* SX  = sx[wid];
    float* ST1 = st1[wid];
    float* SD  = sdeg[wid];

    #pragma unroll
    for (int i = 0; i < 33; ++i) L[i*32 + lane] = 0.f;
    #pragma unroll
    for (int r = 0; r < 5; ++r) SX[r*32 + lane] = x[(size_t)nb*FFc + r*32 + lane];
    SD[lane] = 0.f;
    __syncwarp();

    int es[8], ed[8];
    float ew[8];
    #pragma unroll
    for (int r = 0; r < 8; ++r){
        const int e = g*EPGc + r*32 + lane;
        es[r] = ei[e]        - nb;
        ed[r] = ei[ETOT + e] - nb;
        ew[r] = ea[e];
        atomicAdd(&SD[es[r]], ew[r]);
    }
    __syncwarp();
    {
        float dv = SD[lane];
        dv = (dv > 0.f) ? rsqrtf(dv) : 0.f;
        __syncwarp();
        SD[lane] = dv;
    }
    __syncwarp();
    #pragma unroll
    for (int r = 0; r < 8; ++r){
        const float nrm = -SD[es[r]] * ew[r] * SD[ed[r]];
        atomicAdd(&L[ed[r]*33 + es[r]], nrm);
    }
    __syncwarp();

    float t1f[5] = {0,0,0,0,0};
    #pragma unroll 4
    for (int s = 0; s < 32; ++s){
        const float l = L[lane*33 + s];
        #pragma unroll
        for (int f = 0; f < 5; ++f) t1f[f] += l * SX[s*5 + f];
    }
    #pragma unroll
    for (int f = 0; f < 5; ++f) ST1[lane*5 + f] = t1f[f];
    __syncwarp();

    float t2f[5] = {0,0,0,0,0};
    #pragma unroll 4
    for (int s = 0; s < 32; ++s){
        const float l = L[lane*33 + s];
        #pragma unroll
        for (int f = 0; f < 5; ++f) t2f[f] += l * ST1[s*5 + f];
    }
    float x0[5];
    #pragma unroll
    for (int f = 0; f < 5; ++f){
        x0[f] = SX[lane*5 + f];
        t2f[f] = 2.f*t2f[f] - x0[f];
    }

    float o[5], s2[5];
    #pragma unroll
    for (int j = 0; j < 5; ++j) o[j] = __ldg(&cb[j]);
    #pragma unroll
    for (int i = 0; i < 5; ++i){
        #pragma unroll
        for (int j = 0; j < 5; ++j)
            o[j] += x0[i]*__ldg(&cw[i*5+j]) + t1f[i]*__ldg(&cw[25+i*5+j]) + t2f[i]*__ldg(&cw[50+i*5+j]);
    }
    #pragma unroll
    for (int j = 0; j < 5; ++j){
        g_y[(size_t)nb*FFc + lane*FFc + j] = o[j];
        s2[j] = o[j]*o[j];
    }
    float s1[5];
    #pragma unroll
    for (int j = 0; j < 5; ++j) s1[j] = o[j];
    #pragma unroll
    for (int off = 16; off; off >>= 1){
        #pragma unroll
        for (int j = 0; j < 5; ++j){
            s1[j] += __shfl_xor_sync(0xffffffffu, s1[j], off);
            s2[j] += __shfl_xor_sync(0xffffffffu, s2[j], off);
        }
    }
    if (lane == 0){
        #pragma unroll
        for (int j = 0; j < 5; ++j){
            atomicAdd(&g_stat[b*16 + j],     s1[j]);
            atomicAdd(&g_stat[b*16 + 8 + j], s2[j]);
        }
    }
}

// ==================== Kernel 2: BN transform (stats precomputed) =====================
__global__ __launch_bounds__(256) void bn_kernel(
    const float* __restrict__ gamma, const float* __restrict__ beta)
{
    const int b = blockIdx.x, tid = threadIdx.x;
    __shared__ float sc[5], sh[5];
    if (tid < 5){
        const float inv = 1.f / (float)(TT*NPGc);
        const float mean = g_stat[b*16 + tid] * inv;
        const float var  = g_stat[b*16 + 8 + tid] * inv - mean*mean;
        const float scl  = gamma[tid] * rsqrtf(var + 1e-5f);
        sc[tid] = scl; sh[tid] = beta[tid] - mean*scl;
    }
    __syncthreads();
    const float* yb = g_y + (size_t)b * TSEQ;
    __half2* hz = (__half2*)(g_hx + (size_t)b*KPAD);
    for (int j = tid; j < HHc/2; j += 256) hz[j] = __half2half2(__float2half(0.f));
    for (int j = tid; j < TT*(KPAD-KTOT); j += 256){
        const int t = j / (KPAD-KTOT), c = j % (KPAD-KTOT);
        g_hx[(size_t)t*SLOT + (size_t)b*KPAD + KTOT + c] = __float2half(0.f);
    }
    for (int nidx = tid; nidx < TT*NPGc; nidx += 256){
        const int t = nidx >> 5, node = nidx & 31;
        const float* p = yb + nidx*FFc;
        __half* ob = g_hx + (size_t)t*SLOT + (size_t)b*KPAD + HHc + node*FFc;
        #pragma unroll
        for (int f = 0; f < 5; ++f) ob[f] = __float2half(sigmf(p[f]*sc[f] + sh[f]));
    }
}

// ==================== Kernel 3: persistent LSTM (exact round-5 core) =================
__global__ __launch_bounds__(256, 1) void lstm_persist_kernel()
{
    extern __shared__ char smem[];
    float* sbias = (float*)(smem + SOFF_BIAS);
    char*  Asm   = smem + SOFF_A;
    char*  Wsm   = smem + SOFF_W;

    const int tid  = threadIdx.x;
    const int lane = tid & 31, warp = tid >> 5;
    const int wm = warp >> 1, wn = warp & 1;          // 4 x 2 warp grid
    const int hblk  = blockIdx.x;                     // 16
    const int mgrp  = blockIdx.y;                     // 8
    const int mbase = mgrp * 128;
    const int hbase = hblk * 32;

    // ---- weights (128 x 704 half) into swizzled smem, once ----
    const __half* Bg = g_Wc + (size_t)(hblk*128)*KPAD;
    for (int i = tid; i < 128*NCHUNK*8; i += 256){
        const int r = i / (NCHUNK*8);
        const int rem = i - r*(NCHUNK*8);
        const int c = rem >> 3, j = rem & 7;
        cpasync16(Wsm + c*16384 + swz((uint32_t)r*128 + j*16),
                  Bg + (size_t)r*KPAD + c*64 + j*8);
    }
    if (tid < 128) sbias[tid] = g_bc[hblk*128 + tid];
    cp_commit();                                       // group: W

    auto fillA = [&](int chunk, int stage, const __half* Ag){
        char* dst = Asm + stage*16384;
        const __half* src = Ag + chunk*64;
        #pragma unroll
        for (int p = 0; p < 4; ++p){
            const int idx = tid + p*256;
            const int r = idx >> 3, j = idx & 7;
            cpasync16(dst + swz((uint32_t)r*128 + j*16), src + (size_t)r*KPAD + j*8);
        }
        cp_commit();
    };

    // prologue: step 0 chunks 8,9 -> stages 0,1
    {
        const __half* Ag0 = g_hx + (size_t)mbase*KPAD;
        fillA(8, 0, Ag0);
        fillA(9, 1, Ag0);
    }

    float c_reg[2][2][4];
    #pragma unroll
    for (int a=0;a<2;a++) for (int b=0;b<2;b++) for (int e=0;e<4;e++) c_reg[a][b][e]=0.f;

    const int gl = lane >> 2, tl = lane & 3;
    int stg = 0;   // stage of chunk being computed this iteration

    for (int t = 0; t < TT; ++t){
        const __half* Ag  = g_hx + (size_t)t*SLOT + (size_t)mbase*KPAD;
        const __half* Agn = g_hx + (size_t)(t+1)*SLOT + (size_t)mbase*KPAD;

        float acc[2][4][2][4];
        #pragma unroll
        for (int a=0;a<2;a++) for (int b=0;b<4;b++) for (int c=0;c<2;c++)
            #pragma unroll
            for (int d=0;d<4;d++) acc[a][b][c][d]=0.f;

        for (int q = 0; q < NCHUNK; ++q){
            if (t == TT-1 && q == NCHUNK-1) cp_wait<0>(); else cp_wait<1>();
            __syncthreads();

            // issue fill for iteration q+2 (stage (stg+2)%3)
            if (!(t == TT-1 && q >= 9)){
                const int fstage = (stg + 2 >= 3) ? stg - 1 : stg + 2;
                if (q == 0){
                    fillA(10, fstage, Ag);
                } else if (q <= 8){
                    if (q == 1 && t > 0){
                        // wait for all 16 producers of this m-group to publish step t h
                        const unsigned* fp = &g_flag[mgrp][0];
                        unsigned ok;
                        do {
                            unsigned f0,f1,f2,f3,f4,f5,f6,f7;
                            asm volatile("ld.relaxed.gpu.v4.u32 {%0,%1,%2,%3}, [%4];"
                                : "=r"(f0),"=r"(f1),"=r"(f2),"=r"(f3) : "l"(fp));
                            asm volatile("ld.relaxed.gpu.v4.u32 {%0,%1,%2,%3}, [%4];"
                                : "=r"(f4),"=r"(f5),"=r"(f6),"=r"(f7) : "l"(fp+4));
                            unsigned g0,g1,g2,g3,g4,g5,g6,g7;
                            asm volatile("ld.relaxed.gpu.v4.u32 {%0,%1,%2,%3}, [%4];"
                                : "=r"(g0),"=r"(g1),"=r"(g2),"=r"(g3) : "l"(fp+8));
                            asm volatile("ld.relaxed.gpu.v4.u32 {%0,%1,%2,%3}, [%4];"
                                : "=r"(g4),"=r"(g5),"=r"(g6),"=r"(g7) : "l"(fp+12));
                            unsigned mn = min(min(min(f0,f1),min(f2,f3)), min(min(f4,f5),min(f6,f7)));
                            mn = min(mn, min(min(min(g0,g1),min(g2,g3)), min(min(g4,g5),min(g6,g7))));
                            ok = (mn >= (unsigned)t);
                        } while (!ok);
                        __threadfence();
                    }
                    fillA(q-1, fstage, Ag);            // h chunks 0..7 of step t
                } else {
                    fillA(q-1, fstage, Agn);           // chunks 8,9 of step t+1 (seq only)
                }
            }

            // compute chunk order[q] from stage stg
            const int c = (q < 3) ? q + 8 : q - 3;
            const char* Wc = Wsm + c*16384;
            const char* Ac = Asm + stg*16384;
            #pragma unroll
            for (int kk = 0; kk < 4; ++kk){
                uint32_t af[2][4];
                #pragma unroll
                for (int mf = 0; mf < 2; ++mf){
                    const uint32_t off = (uint32_t)(wm*32 + mf*16 + (lane&15))*128
                                       + (uint32_t)(kk*16 + ((lane>>4)<<3))*2;
                    ldm_x4(af[mf], Ac + swz(off));
                }
                uint32_t bf[4][4];
                #pragma unroll
                for (int g = 0; g < 4; ++g){
                    const uint32_t off = (uint32_t)(g*32 + wn*16 + (lane&7) + ((lane>>4)&1)*8)*128
                                       + (uint32_t)(kk*16 + ((lane>>3)&1)*8)*2;
                    ldm_x4(bf[g], Wc + swz(off));
                }
                #pragma unroll
                for (int mf = 0; mf < 2; ++mf)
                    #pragma unroll
                    for (int g = 0; g < 4; ++g){
                        mma_f16(acc[mf][g][0], af[mf], bf[g] + 0);
                        mma_f16(acc[mf][g][1], af[mf], bf[g] + 2);
                    }
            }
            stg = (stg + 1 >= 3) ? 0 : stg + 1;
        }

        // epilogue: gates -> c (regs) -> h (half) into slot t+1
        __half* h_out = g_hx + (size_t)(t+1)*SLOT;
        #pragma unroll
        for (int mf = 0; mf < 2; ++mf){
            #pragma unroll
            for (int nf = 0; nf < 2; ++nf){
                const int hloc0 = wn*16 + nf*8 + tl*2;
                #pragma unroll
                for (int rr = 0; rr < 2; ++rr){
                    const int row = mbase + wm*32 + mf*16 + gl + rr*8;
                    float hv[2];
                    #pragma unroll
                    for (int j = 0; j < 2; ++j){
                        const int e = rr*2 + j;
                        const int hl = hloc0 + j;
                        const float iv = acc[mf][0][nf][e] + sbias[hl];
                        const float fv = acc[mf][1][nf][e] + sbias[32 + hl];
                        const float gv = acc[mf][2][nf][e] + sbias[64 + hl];
                        const float ov = acc[mf][3][nf][e] + sbias[96 + hl];
                        const float cn = sigmf(fv)*c_reg[mf][nf][e] + sigmf(iv)*tanhfast(gv);
                        c_reg[mf][nf][e] = cn;
                        hv[j] = sigmf(ov)*tanhfast(cn);
                    }
                    *(__half2*)(h_out + (size_t)row*KPAD + hbase + hloc0) =
                        __halves2half2(__float2half(hv[0]), __float2half(hv[1]));
                }
            }
        }

        // publish h for step t+1 consumers
        __syncthreads();
        if (tid == 0){
            __threadfence();
            asm volatile("st.relaxed.gpu.u32 [%0], %1;"
                :: "l"(&g_flag[mgrp][hblk]), "r"((unsigned)(t+1)) : "memory");
        }
    }

    // reset flags for the next replay (last block to finish)
    __syncthreads();
    if (tid == 0){
        const unsigned d = atomicAdd(&g_done, 1u);
        if (d == 127u){
            for (int i = 0; i < 8; ++i)
                for (int j = 0; j < 16; ++j) g_flag[i][j] = 0u;
            g_done = 0u;
            __threadfence();
        }
    }
}

// ==================== Kernel 4: final linear, 8 samples per block ====================
__global__ __launch_bounds__(256) void final_kernel(
    const float* __restrict__ linW, const float* __restrict__ linb,
    float* __restrict__ outp)
{
    const int tid = threadIdx.x, lane = tid & 31, warp = tid >> 5;
    const int b0 = blockIdx.x * 8;
    float acc[8][4];
    #pragma unroll
    for (int s = 0; s < 8; ++s)
        #pragma unroll
        for (int o = 0; o < 4; ++o) acc[s][o] = 0.f;

    for (int idx = tid; idx < TT*HHc; idx += 256){
        const int tq = idx >> 9, h = idx & 511;
        const float w0 = __ldg(&linW[idx]);
        const float w1 = __ldg(&linW[TT*HHc + idx]);
        const float w2 = __ldg(&linW[2*TT*HHc + idx]);
        const float w3 = __ldg(&linW[3*TT*HHc + idx]);
        const __half* hp = g_hx + (size_t)(tq+1)*SLOT + h;
        #pragma unroll
        for (int s = 0; s < 8; ++s){
            const float v = sigmf(__half2float(hp[(size_t)(b0+s)*KPAD]));
            acc[s][0] += v*w0; acc[s][1] += v*w1;
            acc[s][2] += v*w2; acc[s][3] += v*w3;
        }
    }
    #pragma unroll
    for (int off = 16; off; off >>= 1)
        #pragma unroll
        for (int s = 0; s < 8; ++s)
            #pragma unroll
            for (int o = 0; o < 4; ++o)
                acc[s][o] += __shfl_xor_sync(0xffffffffu, acc[s][o], off);

    __shared__ float red[8][32];
    if (lane == 0){
        #pragma unroll
        for (int s = 0; s < 8; ++s)
            #pragma unroll
            for (int o = 0; o < 4; ++o) red[warp][s*4+o] = acc[s][o];
    }
    __syncthreads();
    if (tid < 32){
        float sum = 0.f;
        #pragma unroll
        for (int w = 0; w < 8; ++w) sum += red[w][tid];
        const int s = tid >> 2, o = tid & 3;
        outp[(b0 + s)*4 + o] = sigmf(sum + __ldg(&linb[o]));
    }
}

// =====================================================================================
extern "C" void kernel_launch(void* const* d_in, const int* in_sizes, int n_in,
                              void* d_out, int out_size)
{
    const float* x     = (const float*)d_in[0];
    const float* ea    = (const float*)d_in[1];
    const float* cw    = (const float*)d_in[2];
    const float* cb    = (const float*)d_in[3];
    const float* gamma = (const float*)d_in[4];
    const float* beta  = (const float*)d_in[5];
    const float* Wih   = (const float*)d_in[6];
    const float* Whh   = (const float*)d_in[7];
    const float* bih   = (const float*)d_in[8];
    const float* bhh   = (const float*)d_in[9];
    const float* linW  = (const float*)d_in[10];
    const float* linb  = (const float*)d_in[11];
    const int*   ei    = (const int*)  d_in[12];
    float* outp = (float*)d_out;

    cudaFuncSetAttribute(lstm_persist_kernel,
        cudaFuncAttributeMaxDynamicSharedMemorySize, SMEM_SZ);

    pack_kernel<<<1024, 256>>>(Wih, Whh, bih, bhh);
    cheb_kernel<<<NGRAPH/8, 256>>>(x, ea, ei, cw, cb);
    bn_kernel<<<NB, 256>>>(gamma, beta);
    lstm_persist_kernel<<<dim3(16, 8), 256, SMEM_SZ>>>();
    final_kernel<<<NB/8, 256>>>(linW, linb, outp);
}

// round 10
// speedup vs baseline: 1.2924x; 1.2045x over previous
#include <cuda_runtime.h>
#include <cuda_fp16.h>
#include <cstdint>

#define NB   1024
#define TT   48
#define NPGc 32
#define FFc  5
#define HHc  512
#define EPGc 256
#define NTOT (NB*TT*NPGc)
#define ETOT (NB*TT*EPGc)
#define NGRAPH (NB*TT)
#define SEQW 160
#define TSEQ (TT*SEQW)
#define KTOT 672
#define KPAD 704                   // 11 full chunks of 64, 128B-aligned rows
#define SLOT ((size_t)NB*KPAD)
#define NCHUNK 11

// dynamic smem layout for lstm kernel
#define SOFF_BIAS 0                // 512 B
#define SOFF_A    1024             // 3 stages x 16384
#define SOFF_W    (1024 + 3*16384) // 11 chunks x 16384
#define SMEM_SZ   (SOFF_W + NCHUNK*16384)   // 230400 B

// ---------------- static device scratch --------------------------------------------
__device__ __align__(128) float  g_y  [NTOT*FFc];
__device__ __align__(128) __half g_hx [49*NB*KPAD];   // [t][B][ h(512) | seq(160) | pad ]
__device__ __align__(128) __half g_Wc [4*HHc*KPAD];   // packed [Whh|Wih|0] half
__device__ __align__(128) float  g_bc [4*HHc];
__device__ __align__(128) float  g_stat[NB*16];
__device__ __align__(128) unsigned g_flag[8][16];     // [mgrp][hblk] step counters
__device__ unsigned g_done = 0;

__device__ __forceinline__ float sigmf(float x){ return __fdividef(1.f, 1.f + __expf(-x)); }
__device__ __forceinline__ float tanhfast(float x){
    const float e = __expf(2.f*x);
    return 1.f - __fdividef(2.f, e + 1.f);
}

__device__ __forceinline__ void cpasync16(void* dst, const void* src){
    uint32_t d = (uint32_t)__cvta_generic_to_shared(dst);
    asm volatile("cp.async.cg.shared.global [%0], [%1], 16;\n" :: "r"(d), "l"(src));
}
__device__ __forceinline__ void cp_commit(){ asm volatile("cp.async.commit_group;\n"); }
template<int N> __device__ __forceinline__ void cp_wait(){
    asm volatile("cp.async.wait_group %0;\n" :: "n"(N));
}
__device__ __forceinline__ void ldm_x4(uint32_t* r, const void* p){
    uint32_t a = (uint32_t)__cvta_generic_to_shared(p);
    asm volatile("ldmatrix.sync.aligned.m8n8.x4.shared.b16 {%0,%1,%2,%3}, [%4];"
        : "=r"(r[0]), "=r"(r[1]), "=r"(r[2]), "=r"(r[3]) : "r"(a));
}
__device__ __forceinline__ void mma_f16(float* d, const uint32_t* a, const uint32_t* b){
    asm volatile("mma.sync.aligned.m16n8k16.row.col.f32.f16.f16.f32 "
        "{%0,%1,%2,%3}, {%4,%5,%6,%7}, {%8,%9}, {%0,%1,%2,%3};"
        : "+f"(d[0]), "+f"(d[1]), "+f"(d[2]), "+f"(d[3])
        : "r"(a[0]), "r"(a[1]), "r"(a[2]), "r"(a[3]), "r"(b[0]), "r"(b[1]));
}
__device__ __forceinline__ uint32_t swz(uint32_t off){ return off ^ ((off >> 3) & 0x70); }

// ==================== Kernel 0: pack weights (+bias) to half; zero stats =============
__global__ __launch_bounds__(256) void pack_kernel(
    const float* __restrict__ Wih, const float* __restrict__ Whh,
    const float* __restrict__ bih, const float* __restrict__ bhh)
{
    int idx = blockIdx.x*256 + threadIdx.x;
    if (idx < NB*16) g_stat[idx] = 0.f;
    const int total = 4*HHc*KPAD;
    for (; idx < total; idx += gridDim.x*256){
        const int R = idx / KPAD, k = idx - R*KPAD;
        const int hblk = R >> 7, within = R & 127;
        const int g = within >> 5, hloc = within & 31;
        const int p = g*HHc + hblk*32 + hloc;
        float v = 0.f;
        if (k < HHc)       v = Whh[(size_t)p*HHc + k];
        else if (k < KTOT) v = Wih[(size_t)p*SEQW + (k-HHc)];
        g_Wc[idx] = __float2half(v);
        if (k == 0) g_bc[R] = bih[p] + bhh[p];
    }
}

// ==================== Kernel 1: ChebConv — dense L per graph, warp per graph =========
__global__ __launch_bounds__(256) void cheb_kernel(
    const float* __restrict__ x, const float* __restrict__ ea,
    const int* __restrict__ ei, const float* __restrict__ cw,
    const float* __restrict__ cb)
{
    __shared__ float sL[8][32*33];
    __shared__ float sx[8][160], st1[8][160], sdeg[8][32];
    const int tid = threadIdx.x, lane = tid & 31, wid = tid >> 5;
    const int g  = blockIdx.x*8 + wid;
    const int nb = g * NPGc;
    const int b  = g / TT;
    float* L   = sL[wid];
    float* SX  = sx[wid];
    float* ST1 = st1[wid];
    float* SD  = sdeg[wid];

    #pragma unroll
    for (int i = 0; i < 33; ++i) L[i*32 + lane] = 0.f;
    #pragma unroll
    for (int r = 0; r < 5; ++r) SX[r*32 + lane] = x[(size_t)nb*FFc + r*32 + lane];
    SD[lane] = 0.f;
    __syncwarp();

    int es[8], ed[8];
    float ew[8];
    #pragma unroll
    for (int r = 0; r < 8; ++r){
        const int e = g*EPGc + r*32 + lane;
        es[r] = ei[e]        - nb;
        ed[r] = ei[ETOT + e] - nb;
        ew[r] = ea[e];
        atomicAdd(&SD[es[r]], ew[r]);
    }
    __syncwarp();
    {
        float dv = SD[lane];
        dv = (dv > 0.f) ? rsqrtf(dv) : 0.f;
        __syncwarp();
        SD[lane] = dv;
    }
    __syncwarp();
    #pragma unroll
    for (int r = 0; r < 8; ++r){
        const float nrm = -SD[es[r]] * ew[r] * SD[ed[r]];
        atomicAdd(&L[ed[r]*33 + es[r]], nrm);
    }
    __syncwarp();

    float t1f[5] = {0,0,0,0,0};
    #pragma unroll 4
    for (int s = 0; s < 32; ++s){
        const float l = L[lane*33 + s];
        #pragma unroll
        for (int f = 0; f < 5; ++f) t1f[f] += l * SX[s*5 + f];
    }
    #pragma unroll
    for (int f = 0; f < 5; ++f) ST1[lane*5 + f] = t1f[f];
    __syncwarp();

    float t2f[5] = {0,0,0,0,0};
    #pragma unroll 4
    for (int s = 0; s < 32; ++s){
        const float l = L[lane*33 + s];
        #pragma unroll
        for (int f = 0; f < 5; ++f) t2f[f] += l * ST1[s*5 + f];
    }
    float x0[5];
    #pragma unroll
    for (int f = 0; f < 5; ++f){
        x0[f] = SX[lane*5 + f];
        t2f[f] = 2.f*t2f[f] - x0[f];
    }

    float o[5], s2[5];
    #pragma unroll
    for (int j = 0; j < 5; ++j) o[j] = __ldg(&cb[j]);
    #pragma unroll
    for (int i = 0; i < 5; ++i){
        #pragma unroll
        for (int j = 0; j < 5; ++j)
            o[j] += x0[i]*__ldg(&cw[i*5+j]) + t1f[i]*__ldg(&cw[25+i*5+j]) + t2f[i]*__ldg(&cw[50+i*5+j]);
    }
    #pragma unroll
    for (int j = 0; j < 5; ++j){
        g_y[(size_t)nb*FFc + lane*FFc + j] = o[j];
        s2[j] = o[j]*o[j];
    }
    float s1[5];
    #pragma unroll
    for (int j = 0; j < 5; ++j) s1[j] = o[j];
    #pragma unroll
    for (int off = 16; off; off >>= 1){
        #pragma unroll
        for (int j = 0; j < 5; ++j){
            s1[j] += __shfl_xor_sync(0xffffffffu, s1[j], off);
            s2[j] += __shfl_xor_sync(0xffffffffu, s2[j], off);
        }
    }
    if (lane == 0){
        #pragma unroll
        for (int j = 0; j < 5; ++j){
            atomicAdd(&g_stat[b*16 + j],     s1[j]);
            atomicAdd(&g_stat[b*16 + 8 + j], s2[j]);
        }
    }
}

// ==================== Kernel 2: BN transform (stats precomputed) =====================
__global__ __launch_bounds__(256) void bn_kernel(
    const float* __restrict__ gamma, const float* __restrict__ beta)
{
    const int b = blockIdx.x, tid = threadIdx.x;
    __shared__ float sc[5], sh[5];
    if (tid < 5){
        const float inv = 1.f / (float)(TT*NPGc);
        const float mean = g_stat[b*16 + tid] * inv;
        const float var  = g_stat[b*16 + 8 + tid] * inv - mean*mean;
        const float scl  = gamma[tid] * rsqrtf(var + 1e-5f);
        sc[tid] = scl; sh[tid] = beta[tid] - mean*scl;
    }
    __syncthreads();
    const float* yb = g_y + (size_t)b * TSEQ;
    __half2* hz = (__half2*)(g_hx + (size_t)b*KPAD);
    for (int j = tid; j < HHc/2; j += 256) hz[j] = __half2half2(__float2half(0.f));
    for (int j = tid; j < TT*(KPAD-KTOT); j += 256){
        const int t = j / (KPAD-KTOT), c = j % (KPAD-KTOT);
        g_hx[(size_t)t*SLOT + (size_t)b*KPAD + KTOT + c] = __float2half(0.f);
    }
    for (int nidx = tid; nidx < TT*NPGc; nidx += 256){
        const int t = nidx >> 5, node = nidx & 31;
        const float* p = yb + nidx*FFc;
        __half* ob = g_hx + (size_t)t*SLOT + (size_t)b*KPAD + HHc + node*FFc;
        #pragma unroll
        for (int f = 0; f < 5; ++f) ob[f] = __float2half(sigmf(p[f]*sc[f] + sh[f]));
    }
}

// ==================== Kernel 3: persistent LSTM (exact round-5 core) =================
__global__ __launch_bounds__(256, 1) void lstm_persist_kernel()
{
    extern __shared__ char smem[];
    float* sbias = (float*)(smem + SOFF_BIAS);
    char*  Asm   = smem + SOFF_A;
    char*  Wsm   = smem + SOFF_W;

    const int tid  = threadIdx.x;
    const int lane = tid & 31, warp = tid >> 5;
    const int wm = warp >> 1, wn = warp & 1;          // 4 x 2 warp grid
    const int hblk  = blockIdx.x;                     // 16
    const int mgrp  = blockIdx.y;                     // 8
    const int mbase = mgrp * 128;
    const int hbase = hblk * 32;

    // ---- weights (128 x 704 half) into swizzled smem, once ----
    const __half* Bg = g_Wc + (size_t)(hblk*128)*KPAD;
    for (int i = tid; i < 128*NCHUNK*8; i += 256){
        const int r = i / (NCHUNK*8);
        const int rem = i - r*(NCHUNK*8);
        const int c = rem >> 3, j = rem & 7;
        cpasync16(Wsm + c*16384 + swz((uint32_t)r*128 + j*16),
                  Bg + (size_t)r*KPAD + c*64 + j*8);
    }
    if (tid < 128) sbias[tid] = g_bc[hblk*128 + tid];
    cp_commit();                                       // group: W

    auto fillA = [&](int chunk, int stage, const __half* Ag){
        char* dst = Asm + stage*16384;
        const __half* src = Ag + chunk*64;
        #pragma unroll
        for (int p = 0; p < 4; ++p){
            const int idx = tid + p*256;
            const int r = idx >> 3, j = idx & 7;
            cpasync16(dst + swz((uint32_t)r*128 + j*16), src + (size_t)r*KPAD + j*8);
        }
        cp_commit();
    };

    // prologue: step 0 chunks 8,9 -> stages 0,1
    {
        const __half* Ag0 = g_hx + (size_t)mbase*KPAD;
        fillA(8, 0, Ag0);
        fillA(9, 1, Ag0);
    }

    float c_reg[2][2][4];
    #pragma unroll
    for (int a=0;a<2;a++) for (int b=0;b<2;b++) for (int e=0;e<4;e++) c_reg[a][b][e]=0.f;

    const int gl = lane >> 2, tl = lane & 3;
    int stg = 0;   // stage of chunk being computed this iteration

    for (int t = 0; t < TT; ++t){
        const __half* Ag  = g_hx + (size_t)t*SLOT + (size_t)mbase*KPAD;
        const __half* Agn = g_hx + (size_t)(t+1)*SLOT + (size_t)mbase*KPAD;

        float acc[2][4][2][4];
        #pragma unroll
        for (int a=0;a<2;a++) for (int b=0;b<4;b++) for (int c=0;c<2;c++)
            #pragma unroll
            for (int d=0;d<4;d++) acc[a][b][c][d]=0.f;

        for (int q = 0; q < NCHUNK; ++q){
            if (t == TT-1 && q == NCHUNK-1) cp_wait<0>(); else cp_wait<1>();
            __syncthreads();

            // issue fill for iteration q+2 (stage (stg+2)%3)
            if (!(t == TT-1 && q >= 9)){
                const int fstage = (stg + 2 >= 3) ? stg - 1 : stg + 2;
                if (q == 0){
                    fillA(10, fstage, Ag);
                } else if (q <= 8){
                    if (q == 1 && t > 0){
                        // wait for all 16 producers of this m-group to publish step t h
                        const unsigned* fp = &g_flag[mgrp][0];
                        unsigned ok;
                        do {
                            unsigned f0,f1,f2,f3,f4,f5,f6,f7;
                            asm volatile("ld.relaxed.gpu.v4.u32 {%0,%1,%2,%3}, [%4];"
                                : "=r"(f0),"=r"(f1),"=r"(f2),"=r"(f3) : "l"(fp));
                            asm volatile("ld.relaxed.gpu.v4.u32 {%0,%1,%2,%3}, [%4];"
                                : "=r"(f4),"=r"(f5),"=r"(f6),"=r"(f7) : "l"(fp+4));
                            unsigned g0,g1,g2,g3,g4,g5,g6,g7;
                            asm volatile("ld.relaxed.gpu.v4.u32 {%0,%1,%2,%3}, [%4];"
                                : "=r"(g0),"=r"(g1),"=r"(g2),"=r"(g3) : "l"(fp+8));
                            asm volatile("ld.relaxed.gpu.v4.u32 {%0,%1,%2,%3}, [%4];"
                                : "=r"(g4),"=r"(g5),"=r"(g6),"=r"(g7) : "l"(fp+12));
                            unsigned mn = min(min(min(f0,f1),min(f2,f3)), min(min(f4,f5),min(f6,f7)));
                            mn = min(mn, min(min(min(g0,g1),min(g2,g3)), min(min(g4,g5),min(g6,g7))));
                            ok = (mn >= (unsigned)t);
                        } while (!ok);
                        __threadfence();
                    }
                    fillA(q-1, fstage, Ag);            // h chunks 0..7 of step t
                } else {
                    fillA(q-1, fstage, Agn);           // chunks 8,9 of step t+1 (seq only)
                }
            }

            // compute chunk order[q] from stage stg
            const int c = (q < 3) ? q + 8 : q - 3;
            const char* Wc = Wsm + c*16384;
            const char* Ac = Asm + stg*16384;
            #pragma unroll
            for (int kk = 0; kk < 4; ++kk){
                uint32_t af[2][4];
                #pragma unroll
                for (int mf = 0; mf < 2; ++mf){
                    const uint32_t off = (uint32_t)(wm*32 + mf*16 + (lane&15))*128
                                       + (uint32_t)(kk*16 + ((lane>>4)<<3))*2;
                    ldm_x4(af[mf], Ac + swz(off));
                }
                uint32_t bf[4][4];
                #pragma unroll
                for (int g = 0; g < 4; ++g){
                    const uint32_t off = (uint32_t)(g*32 + wn*16 + (lane&7) + ((lane>>4)&1)*8)*128
                                       + (uint32_t)(kk*16 + ((lane>>3)&1)*8)*2;
                    ldm_x4(bf[g], Wc + swz(off));
                }
                #pragma unroll
                for (int mf = 0; mf < 2; ++mf)
                    #pragma unroll
                    for (int g = 0; g < 4; ++g){
                        mma_f16(acc[mf][g][0], af[mf], bf[g] + 0);
                        mma_f16(acc[mf][g][1], af[mf], bf[g] + 2);
                    }
            }
            stg = (stg + 1 >= 3) ? 0 : stg + 1;
        }

        // epilogue: gates -> c (regs) -> h (half) into slot t+1
        __half* h_out = g_hx + (size_t)(t+1)*SLOT;
        #pragma unroll
        for (int mf = 0; mf < 2; ++mf){
            #pragma unroll
            for (int nf = 0; nf < 2; ++nf){
                const int hloc0 = wn*16 + nf*8 + tl*2;
                #pragma unroll
                for (int rr = 0; rr < 2; ++rr){
                    const int row = mbase + wm*32 + mf*16 + gl + rr*8;
                    float hv[2];
                    #pragma unroll
                    for (int j = 0; j < 2; ++j){
                        const int e = rr*2 + j;
                        const int hl = hloc0 + j;
                        const float iv = acc[mf][0][nf][e] + sbias[hl];
                        const float fv = acc[mf][1][nf][e] + sbias[32 + hl];
                        const float gv = acc[mf][2][nf][e] + sbias[64 + hl];
                        const float ov = acc[mf][3][nf][e] + sbias[96 + hl];
                        const float cn = sigmf(fv)*c_reg[mf][nf][e] + sigmf(iv)*tanhfast(gv);
                        c_reg[mf][nf][e] = cn;
                        hv[j] = sigmf(ov)*tanhfast(cn);
                    }
                    *(__half2*)(h_out + (size_t)row*KPAD + hbase + hloc0) =
                        __halves2half2(__float2half(hv[0]), __float2half(hv[1]));
                }
            }
        }

        // publish h for step t+1 consumers
        __syncthreads();
        if (tid == 0){
            __threadfence();
            asm volatile("st.relaxed.gpu.u32 [%0], %1;"
                :: "l"(&g_flag[mgrp][hblk]), "r"((unsigned)(t+1)) : "memory");
        }
    }

    // reset flags for the next replay (last block to finish)
    __syncthreads();
    if (tid == 0){
        const unsigned d = atomicAdd(&g_done, 1u);
        if (d == 127u){
            for (int i = 0; i < 8; ++i)
                for (int j = 0; j < 16; ++j) g_flag[i][j] = 0u;
            g_done = 0u;
            __threadfence();
        }
    }
}

// ==================== Kernel 4: final linear, 4 samples per block (R6 version) =======
__global__ __launch_bounds__(256) void final_kernel(
    const float* __restrict__ linW, const float* __restrict__ linb,
    float* __restrict__ outp)
{
    const int tid = threadIdx.x, lane = tid & 31, warp = tid >> 5;
    const int b0 = blockIdx.x * 4;
    float acc[4][4];
    #pragma unroll
    for (int s = 0; s < 4; ++s)
        #pragma unroll
        for (int o = 0; o < 4; ++o) acc[s][o] = 0.f;

    for (int idx = tid; idx < TT*HHc; idx += 256){
        const int tq = idx >> 9, h = idx & 511;
        const float w0 = __ldg(&linW[idx]);
        const float w1 = __ldg(&linW[TT*HHc + idx]);
        const float w2 = __ldg(&linW[2*TT*HHc + idx]);
        const float w3 = __ldg(&linW[3*TT*HHc + idx]);
        const __half* hp = g_hx + (size_t)(tq+1)*SLOT + h;
        #pragma unroll
        for (int s = 0; s < 4; ++s){
            const float v = sigmf(__half2float(hp[(size_t)(b0+s)*KPAD]));
            acc[s][0] += v*w0; acc[s][1] += v*w1;
            acc[s][2] += v*w2; acc[s][3] += v*w3;
        }
    }
    #pragma unroll
    for (int off = 16; off; off >>= 1)
        #pragma unroll
        for (int s = 0; s < 4; ++s)
            #pragma unroll
            for (int o = 0; o < 4; ++o)
                acc[s][o] += __shfl_xor_sync(0xffffffffu, acc[s][o], off);

    __shared__ float red[8][16];
    if (lane == 0){
        #pragma unroll
        for (int s = 0; s < 4; ++s)
            #pragma unroll
            for (int o = 0; o < 4; ++o) red[warp][s*4+o] = acc[s][o];
    }
    __syncthreads();
    if (tid < 16){
        float sum = 0.f;
        #pragma unroll
        for (int w = 0; w < 8; ++w) sum += red[w][tid];
        const int s = tid >> 2, o = tid & 3;
        outp[(b0 + s)*4 + o] = sigmf(sum + __ldg(&linb[o]));
    }
}

// =====================================================================================
extern "C" void kernel_launch(void* const* d_in, const int* in_sizes, int n_in,
                              void* d_out, int out_size)
{
    const float* x     = (const float*)d_in[0];
    const float* ea    = (const float*)d_in[1];
    const float* cw    = (const float*)d_in[2];
    const float* cb    = (const float*)d_in[3];
    const float* gamma = (const float*)d_in[4];
    const float* beta  = (const float*)d_in[5];
    const float* Wih   = (const float*)d_in[6];
    const float* Whh   = (const float*)d_in[7];
    const float* bih   = (const float*)d_in[8];
    const float* bhh   = (const float*)d_in[9];
    const float* linW  = (const float*)d_in[10];
    const float* linb  = (const float*)d_in[11];
    const int*   ei    = (const int*)  d_in[12];
    float* outp = (float*)d_out;

    cudaFuncSetAttribute(lstm_persist_kernel,
        cudaFuncAttributeMaxDynamicSharedMemorySize, SMEM_SZ);

    pack_kernel<<<1024, 256>>>(Wih, Whh, bih, bhh);
    cheb_kernel<<<NGRAPH/8, 256>>>(x, ea, ei, cw, cb);
    bn_kernel<<<NB, 256>>>(gamma, beta);
    lstm_persist_kernel<<<dim3(16, 8), 256, SMEM_SZ>>>();
    final_kernel<<<NB/4, 256>>>(linW, linb, outp);
}